// round 9
// baseline (speedup 1.0000x reference)
#include <cuda_runtime.h>
#include <cstdint>

#define N_NODES 50000
#define DIM     512
#define N_EDGES 1600000
#define NBLK    ((N_NODES + 255) / 256)   // 196

// ---------------- scratch (static __device__, no allocation) ----------------
__device__ int   g_counts [N_NODES];
__device__ int   g_offsets[N_NODES + 1];
__device__ int   g_cursor [N_NODES];
__device__ int   g_bsum   [NBLK];
__device__ int   g_boff   [NBLK];
__device__ int   g_src_sorted[N_EDGES];
__device__ float g_w_sorted  [N_EDGES];
__device__ float g_agg[N_NODES * DIM];   // tf32-rounded aggregation result [M, K]
__device__ float g_Wr [DIM * DIM];       // tf32-rounded W [K, N] (same layout)

// ---------------- helpers ----------------
__device__ __forceinline__ uint32_t smem_u32(const void* p) {
    uint32_t a;
    asm("{ .reg .u64 t; cvta.to.shared.u64 t, %1; cvt.u32.u64 %0, t; }" : "=r"(a) : "l"(p));
    return a;
}
__device__ __forceinline__ uint32_t f2tf32(float f) {
    uint32_t u;
    asm("cvt.rna.tf32.f32 %0, %1;" : "=r"(u) : "f"(f));
    return u;
}
__device__ __forceinline__ void cp16(uint32_t dst, const void* src, uint32_t bytes) {
    asm volatile("cp.async.ca.shared.global [%0], [%1], 16, %2;"
                 :: "r"(dst), "l"(src), "r"(bytes) : "memory");
}
#define CP_COMMIT() asm volatile("cp.async.commit_group;" ::: "memory")
#define CP_WAIT_1() asm volatile("cp.async.wait_group 1;" ::: "memory")
#define CP_WAIT_0() asm volatile("cp.async.wait_group 0;" ::: "memory")

__device__ __forceinline__ void mma_tf32(float* c, const uint32_t* a, const uint32_t* b) {
    asm volatile(
        "mma.sync.aligned.m16n8k8.row.col.f32.tf32.tf32.f32 "
        "{%0,%1,%2,%3}, {%4,%5,%6,%7}, {%8,%9}, {%0,%1,%2,%3};"
        : "+f"(c[0]), "+f"(c[1]), "+f"(c[2]), "+f"(c[3])
        : "r"(a[0]), "r"(a[1]), "r"(a[2]), "r"(a[3]), "r"(b[0]), "r"(b[1]));
}

// ---------------- kernel: histogram of dst into g_counts ----------------
__global__ void hist_kernel(const int* __restrict__ dst) {
    int e = blockIdx.x * blockDim.x + threadIdx.x;
    if (e < N_EDGES) atomicAdd(&g_counts[dst[e]], 1);
}

// ---------------- 3-phase scan ----------------
// S1: per-block reduction of 256 counts
__global__ __launch_bounds__(256) void scan_reduce_kernel() {
    __shared__ int s[256];
    int i = blockIdx.x * 256 + threadIdx.x;
    int v = (i < N_NODES) ? g_counts[i] : 0;
    s[threadIdx.x] = v;
    __syncthreads();
    #pragma unroll
    for (int off = 128; off > 0; off >>= 1) {
        if (threadIdx.x < off) s[threadIdx.x] += s[threadIdx.x + off];
        __syncthreads();
    }
    if (threadIdx.x == 0) g_bsum[blockIdx.x] = s[0];
}

// S2: scan the 196 block sums (single tiny block)
__global__ __launch_bounds__(256) void scan_blocks_kernel() {
    __shared__ int s[256];
    int v = (threadIdx.x < NBLK) ? g_bsum[threadIdx.x] : 0;
    s[threadIdx.x] = v;
    __syncthreads();
    #pragma unroll
    for (int off = 1; off < 256; off <<= 1) {
        int t = (threadIdx.x >= off) ? s[threadIdx.x - off] : 0;
        __syncthreads();
        s[threadIdx.x] += t;
        __syncthreads();
    }
    if (threadIdx.x < NBLK) g_boff[threadIdx.x] = s[threadIdx.x] - v;   // exclusive
    if (threadIdx.x == 255) g_offsets[N_NODES] = s[255];                // total
}

// S3: in-block exclusive scan + block offset -> offsets & cursors
__global__ __launch_bounds__(256) void scan_final_kernel() {
    __shared__ int s[256];
    int i = blockIdx.x * 256 + threadIdx.x;
    int v = (i < N_NODES) ? g_counts[i] : 0;
    s[threadIdx.x] = v;
    __syncthreads();
    #pragma unroll
    for (int off = 1; off < 256; off <<= 1) {
        int t = (threadIdx.x >= off) ? s[threadIdx.x - off] : 0;
        __syncthreads();
        s[threadIdx.x] += t;
        __syncthreads();
    }
    if (i < N_NODES) {
        int pref = s[threadIdx.x] - v + g_boff[blockIdx.x];   // exclusive prefix
        g_offsets[i] = pref;
        g_cursor [i] = pref;
    }
}

// ---------------- kernel: scatter edges into dst buckets ----------------
__global__ void fill_kernel(const int* __restrict__ src,
                            const int* __restrict__ dst,
                            const float* __restrict__ w) {
    int e = blockIdx.x * blockDim.x + threadIdx.x;
    if (e < N_EDGES) {
        int d   = dst[e];
        int pos = atomicAdd(&g_cursor[d], 1);
        g_src_sorted[pos] = src[e];
        g_w_sorted[pos]   = w[e];
    }
}

// ---------------- gather aggregation, 4 edges in flight (+ tf32 round) ----------------
__global__ __launch_bounds__(128) void aggregate_kernel(const float4* __restrict__ x4) {
    const int n   = blockIdx.x;
    const int tid = threadIdx.x;
    const int beg = g_offsets[n];
    const int end = g_offsets[n + 1];

    float4 a0 = make_float4(0.f, 0.f, 0.f, 0.f);
    float4 a1 = make_float4(0.f, 0.f, 0.f, 0.f);
    float4 a2 = make_float4(0.f, 0.f, 0.f, 0.f);
    float4 a3 = make_float4(0.f, 0.f, 0.f, 0.f);

    int e = beg;
    for (; e + 3 < end; e += 4) {
        int   s0 = g_src_sorted[e];
        int   s1 = g_src_sorted[e + 1];
        int   s2 = g_src_sorted[e + 2];
        int   s3 = g_src_sorted[e + 3];
        float w0 = g_w_sorted[e];
        float w1 = g_w_sorted[e + 1];
        float w2 = g_w_sorted[e + 2];
        float w3 = g_w_sorted[e + 3];
        float4 v0 = x4[s0 * 128 + tid];
        float4 v1 = x4[s1 * 128 + tid];
        float4 v2 = x4[s2 * 128 + tid];
        float4 v3 = x4[s3 * 128 + tid];
        a0.x += w0 * v0.x;  a0.y += w0 * v0.y;  a0.z += w0 * v0.z;  a0.w += w0 * v0.w;
        a1.x += w1 * v1.x;  a1.y += w1 * v1.y;  a1.z += w1 * v1.z;  a1.w += w1 * v1.w;
        a2.x += w2 * v2.x;  a2.y += w2 * v2.y;  a2.z += w2 * v2.z;  a2.w += w2 * v2.w;
        a3.x += w3 * v3.x;  a3.y += w3 * v3.y;  a3.z += w3 * v3.z;  a3.w += w3 * v3.w;
    }
    for (; e < end; ++e) {
        int   s0 = g_src_sorted[e];
        float w0 = g_w_sorted[e];
        float4 v0 = x4[s0 * 128 + tid];
        a0.x += w0 * v0.x;  a0.y += w0 * v0.y;  a0.z += w0 * v0.z;  a0.w += w0 * v0.w;
    }
    a0.x += a1.x + a2.x + a3.x;
    a0.y += a1.y + a2.y + a3.y;
    a0.z += a1.z + a2.z + a3.z;
    a0.w += a1.w + a2.w + a3.w;

    float4 r;
    r.x = __uint_as_float(f2tf32(a0.x));
    r.y = __uint_as_float(f2tf32(a0.y));
    r.z = __uint_as_float(f2tf32(a0.z));
    r.w = __uint_as_float(f2tf32(a0.w));
    reinterpret_cast<float4*>(g_agg)[n * 128 + tid] = r;
}

// ---------------- round W to tf32 (elementwise, layout preserved) ----------------
__global__ __launch_bounds__(256) void round_w_kernel(const float4* __restrict__ W4) {
    int i = blockIdx.x * blockDim.x + threadIdx.x;
    float4 v = W4[i];
    float4 r;
    r.x = __uint_as_float(f2tf32(v.x));
    r.y = __uint_as_float(f2tf32(v.y));
    r.z = __uint_as_float(f2tf32(v.z));
    r.w = __uint_as_float(f2tf32(v.w));
    reinterpret_cast<float4*>(g_Wr)[i] = r;
}

// ---------------- tf32 mma.sync GEMM + fused epilogue ----------------
#define BM 128
#define BN 128
#define BK 32
#define NKI (DIM / BK)
#define AS_STRIDE 36
#define BS_STRIDE 132
#define SA_ELEMS (BM * AS_STRIDE)
#define SB_ELEMS (BK * BS_STRIDE)
#define SMEM_FLOATS (2 * SA_ELEMS + 2 * SB_ELEMS)

__device__ __forceinline__ void stage_tiles(
    uint32_t saA, uint32_t saB, const float* __restrict__ A,
    int mBase, int nBase, int k0, int tid)
{
    #pragma unroll
    for (int p = 0; p < 4; ++p) {
        int c    = p * 256 + tid;
        int row  = c >> 3;
        int c4   = c & 7;
        int grow = mBase + row;
        int ok   = (grow < N_NODES);
        const float* src = A + (size_t)(ok ? grow : 0) * DIM + k0 + c4 * 4;
        cp16(saA + (uint32_t)(row * AS_STRIDE + c4 * 4) * 4, src, ok ? 16u : 0u);
    }
    #pragma unroll
    for (int p = 0; p < 4; ++p) {
        int c   = p * 256 + tid;
        int row = c >> 5;
        int c4  = c & 31;
        const float* src = g_Wr + (size_t)(k0 + row) * DIM + nBase + c4 * 4;
        cp16(saB + (uint32_t)(row * BS_STRIDE + c4 * 4) * 4, src, 16u);
    }
}

__global__ __launch_bounds__(256, 2) void mma_gemm_kernel(
    const float* __restrict__ A,
    const float* __restrict__ bias,
    const float* __restrict__ X,
    float* __restrict__ out)
{
    extern __shared__ float sm[];
    const uint32_t sb = smem_u32(sm);
    const uint32_t SA[2] = { sb, sb + SA_ELEMS * 4 };
    const uint32_t SB[2] = { sb + 2 * SA_ELEMS * 4, sb + 2 * SA_ELEMS * 4 + SB_ELEMS * 4 };

    const int tid  = threadIdx.x;
    const int wid  = tid >> 5;
    const int lane = tid & 31;
    const int gid  = lane >> 2;
    const int tig  = lane & 3;
    const int wm   = wid & 3;
    const int wn   = wid >> 2;

    const int mBase = blockIdx.y * BM;
    const int nBase = blockIdx.x * BN;

    float acc[2][8][4];
    #pragma unroll
    for (int i = 0; i < 2; ++i)
        #pragma unroll
        for (int j = 0; j < 8; ++j)
            #pragma unroll
            for (int q = 0; q < 4; ++q) acc[i][j][q] = 0.f;

    stage_tiles(SA[0], SB[0], A, mBase, nBase, 0, tid);
    CP_COMMIT();

    int buf = 0;
    for (int it = 0; it < NKI; ++it) {
        if (it + 1 < NKI) {
            stage_tiles(SA[buf ^ 1], SB[buf ^ 1], A, mBase, nBase, (it + 1) * BK, tid);
            CP_COMMIT();
            CP_WAIT_1();
        } else {
            CP_WAIT_0();
        }
        __syncthreads();

        const uint32_t* AsU = reinterpret_cast<const uint32_t*>(sm) + buf * SA_ELEMS;
        const uint32_t* BsU = reinterpret_cast<const uint32_t*>(sm) + 2 * SA_ELEMS + buf * SB_ELEMS;

        #pragma unroll
        for (int ks = 0; ks < 4; ++ks) {
            const int kk = ks * 8;
            uint32_t a[2][4];
            #pragma unroll
            for (int i = 0; i < 2; ++i) {
                int r0 = wm * 32 + i * 16 + gid;
                a[i][0] = AsU[(r0    ) * AS_STRIDE + kk + tig    ];
                a[i][1] = AsU[(r0 + 8) * AS_STRIDE + kk + tig    ];
                a[i][2] = AsU[(r0    ) * AS_STRIDE + kk + tig + 4];
                a[i][3] = AsU[(r0 + 8) * AS_STRIDE + kk + tig + 4];
            }
            uint32_t b[8][2];
            #pragma unroll
            for (int j = 0; j < 8; ++j) {
                int n0 = wn * 64 + j * 8 + gid;
                b[j][0] = BsU[(kk + tig    ) * BS_STRIDE + n0];
                b[j][1] = BsU[(kk + tig + 4) * BS_STRIDE + n0];
            }
            #pragma unroll
            for (int i = 0; i < 2; ++i)
                #pragma unroll
                for (int j = 0; j < 8; ++j)
                    mma_tf32(acc[i][j], a[i], b[j]);
        }
        __syncthreads();
        buf ^= 1;
    }

    #pragma unroll
    for (int i = 0; i < 2; ++i) {
        int r0 = mBase + wm * 32 + i * 16 + gid;
        int r1 = r0 + 8;
        #pragma unroll
        for (int j = 0; j < 8; ++j) {
            int col = nBase + wn * 64 + j * 8 + tig * 2;
            float2 bb = *reinterpret_cast<const float2*>(&bias[col]);
            if (r0 < N_NODES) {
                float2 xr = *reinterpret_cast<const float2*>(&X[(size_t)r0 * DIM + col]);
                float2 o;
                o.x = fmaxf(acc[i][j][0] + bb.x, 0.f) + xr.x;
                o.y = fmaxf(acc[i][j][1] + bb.y, 0.f) + xr.y;
                *reinterpret_cast<float2*>(&out[(size_t)r0 * DIM + col]) = o;
            }
            if (r1 < N_NODES) {
                float2 xr = *reinterpret_cast<const float2*>(&X[(size_t)r1 * DIM + col]);
                float2 o;
                o.x = fmaxf(acc[i][j][2] + bb.x, 0.f) + xr.x;
                o.y = fmaxf(acc[i][j][3] + bb.y, 0.f) + xr.y;
                *reinterpret_cast<float2*>(&out[(size_t)r1 * DIM + col]) = o;
            }
        }
    }
}

// ---------------- launch ----------------
extern "C" void kernel_launch(void* const* d_in, const int* in_sizes, int n_in,
                              void* d_out, int out_size) {
    const float* x    = (const float*)d_in[0];  // [N, D]
    const float* W    = (const float*)d_in[1];  // [D, D]
    const float* b    = (const float*)d_in[2];  // [D]
    const float* ew   = (const float*)d_in[3];  // [E]
    const int*   esrc = (const int*)  d_in[4];  // [E]
    const int*   edst = (const int*)  d_in[5];  // [E]
    float* out = (float*)d_out;

    float* agg_ptr;
    cudaGetSymbolAddress((void**)&agg_ptr, g_agg);
    int* counts_ptr;
    cudaGetSymbolAddress((void**)&counts_ptr, g_counts);

    cudaFuncSetAttribute(mma_gemm_kernel,
                         cudaFuncAttributeMaxDynamicSharedMemorySize,
                         SMEM_FLOATS * 4);

    cudaMemsetAsync(counts_ptr, 0, N_NODES * sizeof(int), 0);
    hist_kernel<<<N_EDGES / 256, 256>>>(edst);
    round_w_kernel<<<(DIM * DIM / 4) / 256, 256>>>(reinterpret_cast<const float4*>(W));
    scan_reduce_kernel<<<NBLK, 256>>>();
    scan_blocks_kernel<<<1, 256>>>();
    scan_final_kernel<<<NBLK, 256>>>();
    fill_kernel<<<N_EDGES / 256, 256>>>(esrc, edst, ew);
    aggregate_kernel<<<N_NODES, 128>>>(reinterpret_cast<const float4*>(x));

    dim3 ggrid(DIM / BN, (N_NODES + BM - 1) / BM);
    mma_gemm_kernel<<<ggrid, 256, SMEM_FLOATS * 4>>>(agg_ptr, b, x, out);
}

// round 10
// speedup vs baseline: 1.4368x; 1.4368x over previous
#include <cuda_runtime.h>
#include <cstdint>

#define N_NODES 50000
#define DIM     512
#define N_EDGES 1600000
#define NBLK    ((N_NODES + 255) / 256)   // 196

// ---------------- scratch (static __device__, no allocation) ----------------
__device__ int   g_counts [N_NODES];
__device__ int   g_offsets[N_NODES + 1];
__device__ int   g_cursor [N_NODES];
__device__ int   g_bsum   [NBLK];
__device__ int   g_boff   [NBLK];
__device__ int   g_src_sorted[N_EDGES];
__device__ float g_w_sorted  [N_EDGES];
__device__ float g_agg[N_NODES * DIM];   // tf32-rounded aggregation result [M, K]
__device__ float g_Wr [DIM * DIM];       // tf32-rounded W [K, N] (same layout)

// ---------------- helpers ----------------
__device__ __forceinline__ uint32_t smem_u32(const void* p) {
    uint32_t a;
    asm("{ .reg .u64 t; cvta.to.shared.u64 t, %1; cvt.u32.u64 %0, t; }" : "=r"(a) : "l"(p));
    return a;
}
__device__ __forceinline__ uint32_t f2tf32(float f) {
    uint32_t u;
    asm("cvt.rna.tf32.f32 %0, %1;" : "=r"(u) : "f"(f));
    return u;
}
__device__ __forceinline__ void cp16(uint32_t dst, const void* src, uint32_t bytes) {
    asm volatile("cp.async.ca.shared.global [%0], [%1], 16, %2;"
                 :: "r"(dst), "l"(src), "r"(bytes) : "memory");
}
#define CP_COMMIT() asm volatile("cp.async.commit_group;" ::: "memory")
#define CP_WAIT_1() asm volatile("cp.async.wait_group 1;" ::: "memory")
#define CP_WAIT_0() asm volatile("cp.async.wait_group 0;" ::: "memory")

__device__ __forceinline__ void mma_tf32(float* c, const uint32_t* a, const uint32_t* b) {
    asm volatile(
        "mma.sync.aligned.m16n8k8.row.col.f32.tf32.tf32.f32 "
        "{%0,%1,%2,%3}, {%4,%5,%6,%7}, {%8,%9}, {%0,%1,%2,%3};"
        : "+f"(c[0]), "+f"(c[1]), "+f"(c[2]), "+f"(c[3])
        : "r"(a[0]), "r"(a[1]), "r"(a[2]), "r"(a[3]), "r"(b[0]), "r"(b[1]));
}

// ---------------- kernel: histogram of dst into g_counts ----------------
__global__ void hist_kernel(const int* __restrict__ dst) {
    int e = blockIdx.x * blockDim.x + threadIdx.x;
    if (e < N_EDGES) atomicAdd(&g_counts[dst[e]], 1);
}

// ---------------- 3-phase scan ----------------
__global__ __launch_bounds__(256) void scan_reduce_kernel() {
    __shared__ int s[256];
    int i = blockIdx.x * 256 + threadIdx.x;
    int v = (i < N_NODES) ? g_counts[i] : 0;
    s[threadIdx.x] = v;
    __syncthreads();
    #pragma unroll
    for (int off = 128; off > 0; off >>= 1) {
        if (threadIdx.x < off) s[threadIdx.x] += s[threadIdx.x + off];
        __syncthreads();
    }
    if (threadIdx.x == 0) g_bsum[blockIdx.x] = s[0];
}

__global__ __launch_bounds__(256) void scan_blocks_kernel() {
    __shared__ int s[256];
    int v = (threadIdx.x < NBLK) ? g_bsum[threadIdx.x] : 0;
    s[threadIdx.x] = v;
    __syncthreads();
    #pragma unroll
    for (int off = 1; off < 256; off <<= 1) {
        int t = (threadIdx.x >= off) ? s[threadIdx.x - off] : 0;
        __syncthreads();
        s[threadIdx.x] += t;
        __syncthreads();
    }
    if (threadIdx.x < NBLK) g_boff[threadIdx.x] = s[threadIdx.x] - v;   // exclusive
    if (threadIdx.x == 255) g_offsets[N_NODES] = s[255];                // total
}

__global__ __launch_bounds__(256) void scan_final_kernel() {
    __shared__ int s[256];
    int i = blockIdx.x * 256 + threadIdx.x;
    int v = (i < N_NODES) ? g_counts[i] : 0;
    s[threadIdx.x] = v;
    __syncthreads();
    #pragma unroll
    for (int off = 1; off < 256; off <<= 1) {
        int t = (threadIdx.x >= off) ? s[threadIdx.x - off] : 0;
        __syncthreads();
        s[threadIdx.x] += t;
        __syncthreads();
    }
    if (i < N_NODES) {
        int pref = s[threadIdx.x] - v + g_boff[blockIdx.x];   // exclusive prefix
        g_offsets[i] = pref;
        g_cursor [i] = pref;
    }
}

// ---------------- kernel: scatter edges into dst buckets ----------------
__global__ void fill_kernel(const int* __restrict__ src,
                            const int* __restrict__ dst,
                            const float* __restrict__ w) {
    int e = blockIdx.x * blockDim.x + threadIdx.x;
    if (e < N_EDGES) {
        int d   = dst[e];
        int pos = atomicAdd(&g_cursor[d], 1);
        g_src_sorted[pos] = src[e];
        g_w_sorted[pos]   = w[e];
    }
}

// ---------------- gather aggregation, 2 edges in flight (+ tf32 round) ----------------
// (R8 post-mortem: 4-wide regressed via cross-CTA L1tex-queue contention; 2-wide is the sweet spot)
__global__ __launch_bounds__(128) void aggregate_kernel(const float4* __restrict__ x4) {
    const int n   = blockIdx.x;
    const int tid = threadIdx.x;
    const int beg = g_offsets[n];
    const int end = g_offsets[n + 1];

    float4 acc0 = make_float4(0.f, 0.f, 0.f, 0.f);
    float4 acc1 = make_float4(0.f, 0.f, 0.f, 0.f);

    int e = beg;
    for (; e + 1 < end; e += 2) {
        int   s0 = g_src_sorted[e];
        int   s1 = g_src_sorted[e + 1];
        float w0 = g_w_sorted[e];
        float w1 = g_w_sorted[e + 1];
        float4 v0 = x4[s0 * 128 + tid];
        float4 v1 = x4[s1 * 128 + tid];
        acc0.x += w0 * v0.x;  acc0.y += w0 * v0.y;
        acc0.z += w0 * v0.z;  acc0.w += w0 * v0.w;
        acc1.x += w1 * v1.x;  acc1.y += w1 * v1.y;
        acc1.z += w1 * v1.z;  acc1.w += w1 * v1.w;
    }
    if (e < end) {
        int   s0 = g_src_sorted[e];
        float w0 = g_w_sorted[e];
        float4 v0 = x4[s0 * 128 + tid];
        acc0.x += w0 * v0.x;  acc0.y += w0 * v0.y;
        acc0.z += w0 * v0.z;  acc0.w += w0 * v0.w;
    }
    acc0.x += acc1.x; acc0.y += acc1.y; acc0.z += acc1.z; acc0.w += acc1.w;
    float4 r;
    r.x = __uint_as_float(f2tf32(acc0.x));
    r.y = __uint_as_float(f2tf32(acc0.y));
    r.z = __uint_as_float(f2tf32(acc0.z));
    r.w = __uint_as_float(f2tf32(acc0.w));
    reinterpret_cast<float4*>(g_agg)[n * 128 + tid] = r;
}

// ---------------- round W to tf32 (elementwise, layout preserved) ----------------
__global__ __launch_bounds__(256) void round_w_kernel(const float4* __restrict__ W4) {
    int i = blockIdx.x * blockDim.x + threadIdx.x;
    float4 v = W4[i];
    float4 r;
    r.x = __uint_as_float(f2tf32(v.x));
    r.y = __uint_as_float(f2tf32(v.y));
    r.z = __uint_as_float(f2tf32(v.z));
    r.w = __uint_as_float(f2tf32(v.w));
    reinterpret_cast<float4*>(g_Wr)[i] = r;
}

// ---------------- tf32 mma.sync GEMM + fused epilogue ----------------
#define BM 128
#define BN 128
#define BK 32
#define NKI (DIM / BK)
#define AS_STRIDE 36
#define BS_STRIDE 132
#define SA_ELEMS (BM * AS_STRIDE)
#define SB_ELEMS (BK * BS_STRIDE)
#define SMEM_FLOATS (2 * SA_ELEMS + 2 * SB_ELEMS)

__device__ __forceinline__ void stage_tiles(
    uint32_t saA, uint32_t saB, const float* __restrict__ A,
    int mBase, int nBase, int k0, int tid)
{
    #pragma unroll
    for (int p = 0; p < 4; ++p) {
        int c    = p * 256 + tid;
        int row  = c >> 3;
        int c4   = c & 7;
        int grow = mBase + row;
        int ok   = (grow < N_NODES);
        const float* src = A + (size_t)(ok ? grow : 0) * DIM + k0 + c4 * 4;
        cp16(saA + (uint32_t)(row * AS_STRIDE + c4 * 4) * 4, src, ok ? 16u : 0u);
    }
    #pragma unroll
    for (int p = 0; p < 4; ++p) {
        int c   = p * 256 + tid;
        int row = c >> 5;
        int c4  = c & 31;
        const float* src = g_Wr + (size_t)(k0 + row) * DIM + nBase + c4 * 4;
        cp16(saB + (uint32_t)(row * BS_STRIDE + c4 * 4) * 4, src, 16u);
    }
}

__global__ __launch_bounds__(256, 2) void mma_gemm_kernel(
    const float* __restrict__ A,
    const float* __restrict__ bias,
    const float* __restrict__ X,
    float* __restrict__ out)
{
    extern __shared__ float sm[];
    const uint32_t sb = smem_u32(sm);
    const uint32_t SA[2] = { sb, sb + SA_ELEMS * 4 };
    const uint32_t SB[2] = { sb + 2 * SA_ELEMS * 4, sb + 2 * SA_ELEMS * 4 + SB_ELEMS * 4 };

    const int tid  = threadIdx.x;
    const int wid  = tid >> 5;
    const int lane = tid & 31;
    const int gid  = lane >> 2;
    const int tig  = lane & 3;
    const int wm   = wid & 3;
    const int wn   = wid >> 2;

    const int mBase = blockIdx.y * BM;
    const int nBase = blockIdx.x * BN;

    float acc[2][8][4];
    #pragma unroll
    for (int i = 0; i < 2; ++i)
        #pragma unroll
        for (int j = 0; j < 8; ++j)
            #pragma unroll
            for (int q = 0; q < 4; ++q) acc[i][j][q] = 0.f;

    stage_tiles(SA[0], SB[0], A, mBase, nBase, 0, tid);
    CP_COMMIT();

    int buf = 0;
    for (int it = 0; it < NKI; ++it) {
        if (it + 1 < NKI) {
            stage_tiles(SA[buf ^ 1], SB[buf ^ 1], A, mBase, nBase, (it + 1) * BK, tid);
            CP_COMMIT();
            CP_WAIT_1();
        } else {
            CP_WAIT_0();
        }
        __syncthreads();

        const uint32_t* AsU = reinterpret_cast<const uint32_t*>(sm) + buf * SA_ELEMS;
        const uint32_t* BsU = reinterpret_cast<const uint32_t*>(sm) + 2 * SA_ELEMS + buf * SB_ELEMS;

        #pragma unroll
        for (int ks = 0; ks < 4; ++ks) {
            const int kk = ks * 8;
            uint32_t a[2][4];
            #pragma unroll
            for (int i = 0; i < 2; ++i) {
                int r0 = wm * 32 + i * 16 + gid;
                a[i][0] = AsU[(r0    ) * AS_STRIDE + kk + tig    ];
                a[i][1] = AsU[(r0 + 8) * AS_STRIDE + kk + tig    ];
                a[i][2] = AsU[(r0    ) * AS_STRIDE + kk + tig + 4];
                a[i][3] = AsU[(r0 + 8) * AS_STRIDE + kk + tig + 4];
            }
            uint32_t b[8][2];
            #pragma unroll
            for (int j = 0; j < 8; ++j) {
                int n0 = wn * 64 + j * 8 + gid;
                b[j][0] = BsU[(kk + tig    ) * BS_STRIDE + n0];
                b[j][1] = BsU[(kk + tig + 4) * BS_STRIDE + n0];
            }
            #pragma unroll
            for (int i = 0; i < 2; ++i)
                #pragma unroll
                for (int j = 0; j < 8; ++j)
                    mma_tf32(acc[i][j], a[i], b[j]);
        }
        __syncthreads();
        buf ^= 1;
    }

    #pragma unroll
    for (int i = 0; i < 2; ++i) {
        int r0 = mBase + wm * 32 + i * 16 + gid;
        int r1 = r0 + 8;
        #pragma unroll
        for (int j = 0; j < 8; ++j) {
            int col = nBase + wn * 64 + j * 8 + tig * 2;
            float2 bb = *reinterpret_cast<const float2*>(&bias[col]);
            if (r0 < N_NODES) {
                float2 xr = *reinterpret_cast<const float2*>(&X[(size_t)r0 * DIM + col]);
                float2 o;
                o.x = fmaxf(acc[i][j][0] + bb.x, 0.f) + xr.x;
                o.y = fmaxf(acc[i][j][1] + bb.y, 0.f) + xr.y;
                *reinterpret_cast<float2*>(&out[(size_t)r0 * DIM + col]) = o;
            }
            if (r1 < N_NODES) {
                float2 xr = *reinterpret_cast<const float2*>(&X[(size_t)r1 * DIM + col]);
                float2 o;
                o.x = fmaxf(acc[i][j][2] + bb.x, 0.f) + xr.x;
                o.y = fmaxf(acc[i][j][3] + bb.y, 0.f) + xr.y;
                *reinterpret_cast<float2*>(&out[(size_t)r1 * DIM + col]) = o;
            }
        }
    }
}

// ---------------- launch ----------------
extern "C" void kernel_launch(void* const* d_in, const int* in_sizes, int n_in,
                              void* d_out, int out_size) {
    const float* x    = (const float*)d_in[0];  // [N, D]
    const float* W    = (const float*)d_in[1];  // [D, D]
    const float* b    = (const float*)d_in[2];  // [D]
    const float* ew   = (const float*)d_in[3];  // [E]
    const int*   esrc = (const int*)  d_in[4];  // [E]
    const int*   edst = (const int*)  d_in[5];  // [E]
    float* out = (float*)d_out;

    float* agg_ptr;
    cudaGetSymbolAddress((void**)&agg_ptr, g_agg);
    int* counts_ptr;
    cudaGetSymbolAddress((void**)&counts_ptr, g_counts);

    cudaFuncSetAttribute(mma_gemm_kernel,
                         cudaFuncAttributeMaxDynamicSharedMemorySize,
                         SMEM_FLOATS * 4);

    cudaMemsetAsync(counts_ptr, 0, N_NODES * sizeof(int), 0);
    hist_kernel<<<N_EDGES / 256, 256>>>(edst);
    round_w_kernel<<<(DIM * DIM / 4) / 256, 256>>>(reinterpret_cast<const float4*>(W));
    scan_reduce_kernel<<<NBLK, 256>>>();
    scan_blocks_kernel<<<1, 256>>>();
    scan_final_kernel<<<NBLK, 256>>>();
    fill_kernel<<<N_EDGES / 256, 256>>>(esrc, edst, ew);
    aggregate_kernel<<<N_NODES, 128>>>(reinterpret_cast<const float4*>(x));

    dim3 ggrid(DIM / BN, (N_NODES + BM - 1) / BM);
    mma_gemm_kernel<<<ggrid, 256, SMEM_FLOATS * 4>>>(agg_ptr, b, x, out);
}